// round 9
// baseline (speedup 1.0000x reference)
#include <cuda_runtime.h>
#include <cstdint>

#define BB 2
#define CC 64
#define CQ 16
#define DD 96
#define PP 9216                    // H*W
#define PDSTRIDE (PP*DD)           // per-channel stride in x
#define CPD (CC*PDSTRIDE)          // per-batch stride in x
#define PCHUNK 32                  // p per block (energy), 2 per iteration
#define OPB 32                     // p per block (out), 2 per iteration

typedef unsigned long long u64;

__device__ double g_energy[BB*DD*DD];
__device__ int    g_nnz [BB*DD];
__device__ int    g_eidx[BB*DD*DD];
__device__ float  g_aval[BB*DD*DD];

// ---- packed f32x2 helpers (FFMA2 path only reachable via PTX) ----
__device__ __forceinline__ u64 pk2(float lo, float hi) {
    u64 r; asm("mov.b64 %0, {%1, %2};" : "=l"(r) : "f"(lo), "f"(hi)); return r;
}
__device__ __forceinline__ u64 bc2(float v) { return pk2(v, v); }
__device__ __forceinline__ void up2(float& lo, float& hi, u64 v) {
    asm("mov.b64 {%0, %1}, %2;" : "=f"(lo), "=f"(hi) : "l"(v));
}
__device__ __forceinline__ u64 ffma2(u64 a, u64 b, u64 c) {
    u64 d; asm("fma.rn.f32x2 %0, %1, %2, %3;" : "=l"(d) : "l"(a), "l"(b), "l"(c));
    return d;
}

// ===========================================================================
// Kernel A v2: energy[b,d,e] = sum_{p,cq} (Wq X_p + bq)[cq,d]*(Wk X_p + bk)[cq,e]
// 2 slabs per iteration; QK warp-split (each thread: 2 cq x 3 d-pairs, so each
// X load feeds 12 FFMA2); accum over both slabs by all threads (R3 tile).
// ===========================================================================
#define WQS 68                          // padded weight stride (float4-clean)
#define E_WQ 0
#define E_WK (E_WQ + CQ*WQS)            // 1088
#define E_X  (E_WK + CQ*WQS)            // 2176
#define E_Q  (E_X + 2*CC*DD)            // 14464
#define E_K  (E_Q + 2*CQ*DD)            // 17536
#define E_FLOATS (E_K + 2*CQ*DD)        // 20608 floats = 82432 B

__global__ void __launch_bounds__(256, 2) energy_k(
    const float* __restrict__ x,
    const float* __restrict__ Wq, const float* __restrict__ bq,
    const float* __restrict__ Wk, const float* __restrict__ bk)
{
    extern __shared__ __align__(16) float esm[];
    float* sWq = esm + E_WQ;
    float* sWk = esm + E_WK;
    float* sX0 = esm + E_X;             // slab s at +s*CC*DD
    float* sQ0 = esm + E_Q;             // slab s at +s*CQ*DD
    float* sK0 = esm + E_K;

    const int t  = threadIdx.x;
    const int b  = blockIdx.y;
    const int p0 = blockIdx.x * PCHUNK;

    for (int i = t; i < CQ*CC; i += 256) {
        const int cq = i >> 6, c = i & 63;
        sWq[cq*WQS + c] = Wq[i];
        sWk[cq*WQS + c] = Wk[i];
    }

    // QK mapping: slab-half, 2 cq, 6 consecutive d
    const int sh  = t >> 7;             // 0/1
    const int u   = (t >> 4) & 7;       // cq pair {2u, 2u+1}
    const int dxb = 6 * (t & 15);
    const float bq0 = bq[2*u], bq1 = bq[2*u+1];
    const float bk0 = bk[2*u], bk1 = bk[2*u+1];

    // accum mapping: d = tx+16i (scalar), e = 6*ty + 2j (pairs)
    const int tx = t & 15;
    const int ty = t >> 4;

    u64 acc[6][3];
    #pragma unroll
    for (int i = 0; i < 6; ++i)
        #pragma unroll
        for (int j = 0; j < 3; ++j) acc[i][j] = 0ull;

    const float* xb = x + (size_t)b * CPD;

    float4 r4[12];
    // LDG both slabs (3072 float4 across 256 threads -> 12 each)
    #define LDG2(PBASE) {                                                       \
        _Pragma("unroll")                                                       \
        for (int rr = 0; rr < 12; ++rr) {                                       \
            const int idx = t + rr*256;                                         \
            const int s = (rr >= 6);                                            \
            const int j = idx - s*1536;                                         \
            const int c = j / 24, d4 = j - c*24;                                \
            r4[rr] = *reinterpret_cast<const float4*>(                          \
                xb + (size_t)c * PDSTRIDE + (size_t)((PBASE) + s) * DD + 4*d4); } }
    #define STS2() {                                                            \
        _Pragma("unroll")                                                       \
        for (int rr = 0; rr < 12; ++rr) {                                       \
            const int idx = t + rr*256;                                         \
            const int s = (rr >= 6);                                            \
            const int j = idx - s*1536;                                         \
            const int c = j / 24, d4 = j - c*24;                                \
            *reinterpret_cast<float4*>(&sX0[s*(CC*DD) + c*DD + 4*d4]) = r4[rr]; } }

    LDG2(p0);

    for (int it = 0; it < PCHUNK/2; ++it) {
        STS2();
        __syncthreads();

        // ---- QK for my slab: 2 cq x 3 d-pairs, weights via float4/4c ----
        {
            const float* sX = sX0 + sh*(CC*DD);
            u64 qa0[3], qa1[3], ka0[3], ka1[3];
            #pragma unroll
            for (int j = 0; j < 3; ++j) {
                qa0[j] = bc2(bq0); qa1[j] = bc2(bq1);
                ka0[j] = bc2(bk0); ka1[j] = bc2(bk1);
            }
            #pragma unroll 4
            for (int c4 = 0; c4 < CC; c4 += 4) {
                const float4 wq40 = *reinterpret_cast<const float4*>(&sWq[(2*u)*WQS + c4]);
                const float4 wq41 = *reinterpret_cast<const float4*>(&sWq[(2*u+1)*WQS + c4]);
                const float4 wk40 = *reinterpret_cast<const float4*>(&sWk[(2*u)*WQS + c4]);
                const float4 wk41 = *reinterpret_cast<const float4*>(&sWk[(2*u+1)*WQS + c4]);
                const float wq0a[4] = {wq40.x, wq40.y, wq40.z, wq40.w};
                const float wq1a[4] = {wq41.x, wq41.y, wq41.z, wq41.w};
                const float wk0a[4] = {wk40.x, wk40.y, wk40.z, wk40.w};
                const float wk1a[4] = {wk41.x, wk41.y, wk41.z, wk41.w};
                #pragma unroll
                for (int cc = 0; cc < 4; ++cc) {
                    const int c = c4 + cc;
                    u64 xv[3];
                    #pragma unroll
                    for (int j = 0; j < 3; ++j)
                        xv[j] = *reinterpret_cast<const u64*>(&sX[c*DD + dxb + 2*j]);
                    const u64 wqb0 = bc2(wq0a[cc]);
                    const u64 wqb1 = bc2(wq1a[cc]);
                    const u64 wkb0 = bc2(wk0a[cc]);
                    const u64 wkb1 = bc2(wk1a[cc]);
                    #pragma unroll
                    for (int j = 0; j < 3; ++j) {
                        qa0[j] = ffma2(wqb0, xv[j], qa0[j]);
                        qa1[j] = ffma2(wqb1, xv[j], qa1[j]);
                        ka0[j] = ffma2(wkb0, xv[j], ka0[j]);
                        ka1[j] = ffma2(wkb1, xv[j], ka1[j]);
                    }
                }
            }
            float* sQ = sQ0 + sh*(CQ*DD);
            float* sK = sK0 + sh*(CQ*DD);
            #pragma unroll
            for (int j = 0; j < 3; ++j) {
                *reinterpret_cast<u64*>(&sQ[(2*u)*DD   + dxb + 2*j]) = qa0[j];
                *reinterpret_cast<u64*>(&sQ[(2*u+1)*DD + dxb + 2*j]) = qa1[j];
                *reinterpret_cast<u64*>(&sK[(2*u)*DD   + dxb + 2*j]) = ka0[j];
                *reinterpret_cast<u64*>(&sK[(2*u+1)*DD + dxb + 2*j]) = ka1[j];
            }
        }

        if (it + 1 < PCHUNK/2) LDG2(p0 + 2*(it+1));   // overlap with accum
        __syncthreads();

        // ---- accum both slabs (R3 tile, order p-even then p-odd) ----
        #pragma unroll
        for (int s = 0; s < 2; ++s) {
            const float* sQ = sQ0 + s*(CQ*DD);
            const float* sK = sK0 + s*(CQ*DD);
            #pragma unroll 2
            for (int cq = 0; cq < CQ; ++cq) {
                u64 kv[3];
                #pragma unroll
                for (int j = 0; j < 3; ++j)
                    kv[j] = *reinterpret_cast<const u64*>(&sK[cq*DD + 6*ty + 2*j]);
                #pragma unroll
                for (int i = 0; i < 6; ++i) {
                    const u64 qb = bc2(sQ[cq*DD + tx + 16*i]);
                    #pragma unroll
                    for (int j = 0; j < 3; ++j)
                        acc[i][j] = ffma2(qb, kv[j], acc[i][j]);
                }
            }
        }
        __syncthreads();
    }

    const size_t eb = (size_t)b * DD * DD;
    #pragma unroll
    for (int i = 0; i < 6; ++i)
        #pragma unroll
        for (int j = 0; j < 3; ++j) {
            float lo, hi;
            up2(lo, hi, acc[i][j]);
            const size_t base = eb + (size_t)(tx + 16*i)*DD + (6*ty + 2*j);
            atomicAdd(&g_energy[base],     (double)lo);
            atomicAdd(&g_energy[base + 1], (double)hi);
        }
    #undef LDG2
    #undef STS2
}

// ===========================================================================
// Kernel B: row softmax + compaction (a > 1e-8). One warp per (b,d) row.
// ===========================================================================
#define ATHRESH 1e-8f

__global__ void __launch_bounds__(128) softmax_k()
{
    const int w    = (blockIdx.x * blockDim.x + threadIdx.x) >> 5;
    const int lane = threadIdx.x & 31;
    if (w >= BB*DD) return;

    const double* er = g_energy + (size_t)w * DD;
    float v0 = (float)er[lane];
    float v1 = (float)er[lane + 32];
    float v2 = (float)er[lane + 64];

    float m = fmaxf(v0, fmaxf(v1, v2));
    #pragma unroll
    for (int o = 16; o > 0; o >>= 1) m = fmaxf(m, __shfl_xor_sync(0xffffffffu, m, o));

    float e0 = expf(v0 - m), e1 = expf(v1 - m), e2 = expf(v2 - m);
    float s = e0 + e1 + e2;
    #pragma unroll
    for (int o = 16; o > 0; o >>= 1) s += __shfl_xor_sync(0xffffffffu, s, o);

    const float inv = 1.0f / s;
    const float a[3] = { e0 * inv, e1 * inv, e2 * inv };

    int* ei = g_eidx + (size_t)w * DD;
    float* av = g_aval + (size_t)w * DD;
    const unsigned lmask = (1u << lane) - 1u;
    int base = 0;
    #pragma unroll
    for (int sct = 0; sct < 3; ++sct) {
        const bool keep = a[sct] > ATHRESH;
        const unsigned mask = __ballot_sync(0xffffffffu, keep);
        if (keep) {
            const int idx = base + __popc(mask & lmask);
            ei[idx] = lane + 32*sct;
            av[idx] = a[sct];
        }
        base += __popc(mask);
    }
    if (lane == 0) g_nnz[w] = base;
}

// ===========================================================================
// Kernel C v2: out[b,c,p,d] = gamma*sum_{k in list(d)} a_k*V[c,e_k] + x[c,p,d]
// 2 slabs per iteration; V warp-split (each thread 8c x 3 e-pairs -> each X
// load feeds 24 FFMA2); register-cached top-2 sparse gather (R7, proven).
// ===========================================================================
#define WVS 66                          // padded Wv stride (LDS.64-clean)
#define S_WV 0
#define S_X  (S_WV + CC*WVS)            // 4224
#define S_V  (S_X + 2*CC*DD)            // 16512
#define S_FLOATS (S_V + 2*CC*DD)        // 28800 floats = 115200 B

__global__ void __launch_bounds__(256, 2) outs_k(
    const float* __restrict__ x, const float* __restrict__ Wv,
    const float* __restrict__ bv, const float* __restrict__ gamma,
    float* __restrict__ out)
{
    extern __shared__ __align__(16) float osm[];
    float* sWv = osm + S_WV;
    float* sX0 = osm + S_X;             // slab s at +s*CC*DD
    float* sV0 = osm + S_V;             // V[c][e] rows, stride DD

    const int t    = threadIdx.x;
    const int b    = blockIdx.y;
    const int p0   = blockIdx.x * OPB;
    const int sh   = t >> 7;            // slab half
    const int cg   = (t >> 4) & 7;      // c rows 8cg..8cg+7
    const int exb  = 6 * (t & 15);      // e base
    const int lane = t & 31;
    const int wid  = t >> 5;

    for (int i = t; i < CC*CC; i += 256) {
        const int c = i >> 6, c2 = i & 63;
        sWv[c*WVS + c2] = Wv[i];
    }

    // ---- register-cached top-2 attn entries per owned d-row (R7) ----
    int   nL[3], e0L[3], e1L[3];
    float a0L[3], a1L[3];
    #pragma unroll
    for (int dd = 0; dd < 3; ++dd) {
        const int d = lane + 32*dd;
        const int w = b*DD + d;
        const int n = g_nnz[w];
        nL[dd]  = n;
        e0L[dd] = g_eidx[(size_t)w*DD];
        a0L[dd] = g_aval[(size_t)w*DD];
        e1L[dd] = (n > 1) ? g_eidx[(size_t)w*DD + 1] : 0;
        a1L[dd] = (n > 1) ? g_aval[(size_t)w*DD + 1] : 0.f;
    }

    const float g = gamma[0];
    float bvv[8];
    #pragma unroll
    for (int k = 0; k < 8; ++k) bvv[k] = bv[8*cg + k];

    const float* xb = x   + (size_t)b * CPD;
    float*       ob = out + (size_t)b * CPD;

    float4 r4[12];
    #define LDG2(PBASE) {                                                       \
        _Pragma("unroll")                                                       \
        for (int rr = 0; rr < 12; ++rr) {                                       \
            const int idx = t + rr*256;                                         \
            const int s = (rr >= 6);                                            \
            const int j = idx - s*1536;                                         \
            const int c = j / 24, d4 = j - c*24;                                \
            r4[rr] = *reinterpret_cast<const float4*>(                          \
                xb + (size_t)c * PDSTRIDE + (size_t)((PBASE) + s) * DD + 4*d4); } }
    #define STS2() {                                                            \
        _Pragma("unroll")                                                       \
        for (int rr = 0; rr < 12; ++rr) {                                       \
            const int idx = t + rr*256;                                         \
            const int s = (rr >= 6);                                            \
            const int j = idx - s*1536;                                         \
            const int c = j / 24, d4 = j - c*24;                                \
            *reinterpret_cast<float4*>(&sX0[s*(CC*DD) + c*DD + 4*d4]) = r4[rr]; } }

    LDG2(p0);

    for (int it = 0; it < OPB/2; ++it) {
        STS2();
        __syncthreads();

        // ---- V = Wv X + bv for my slab: 8 c x 3 e-pairs per thread ----
        {
            const float* sX = sX0 + sh*(CC*DD);
            u64 vv[8][3];
            #pragma unroll
            for (int k = 0; k < 8; ++k)
                #pragma unroll
                for (int j = 0; j < 3; ++j) vv[k][j] = bc2(bvv[k]);

            #pragma unroll 2
            for (int c2 = 0; c2 < CC; c2 += 2) {
                u64 xA[3], xB[3];
                #pragma unroll
                for (int j = 0; j < 3; ++j) {
                    xA[j] = *reinterpret_cast<const u64*>(&sX[c2*DD + exb + 2*j]);
                    xB[j] = *reinterpret_cast<const u64*>(&sX[(c2+1)*DD + exb + 2*j]);
                }
                #pragma unroll
                for (int k = 0; k < 8; ++k) {
                    const u64 w2 = *reinterpret_cast<const u64*>(&sWv[(8*cg + k)*WVS + c2]);
                    float wlo, whi; up2(wlo, whi, w2);
                    const u64 wb0 = bc2(wlo), wb1 = bc2(whi);
                    #pragma unroll
                    for (int j = 0; j < 3; ++j) {
                        vv[k][j] = ffma2(wb0, xA[j], vv[k][j]);
                        vv[k][j] = ffma2(wb1, xB[j], vv[k][j]);
                    }
                }
            }
            float* sV = sV0 + sh*(CC*DD);
            #pragma unroll
            for (int k = 0; k < 8; ++k)
                #pragma unroll
                for (int j = 0; j < 3; ++j)
                    *reinterpret_cast<u64*>(&sV[(8*cg + k)*DD + exb + 2*j]) = vv[k][j];
        }

        if (it + 1 < OPB/2) LDG2(p0 + 2*(it+1));   // overlap with gather
        __syncthreads();

        // ---- sparse gather both slabs: lanes over d, warps over c ----
        #pragma unroll
        for (int s = 0; s < 2; ++s) {
            const float* sVs = sV0 + s*(CC*DD);
            const float* sXs = sX0 + s*(CC*DD);
            const int p = p0 + 2*it + s;
            #pragma unroll
            for (int ci = 0; ci < 8; ++ci) {
                const int c = wid + 8*ci;
                const float* vrow = &sVs[c*DD];
                const float* xrow = &sXs[c*DD];
                float* orow = ob + (size_t)c * PDSTRIDE + (size_t)p * DD;
                #pragma unroll
                for (int dd = 0; dd < 3; ++dd) {
                    const int d = lane + 32*dd;
                    float acc = a0L[dd] * vrow[e0L[dd]];
                    if (nL[dd] > 1) acc = fmaf(a1L[dd], vrow[e1L[dd]], acc);
                    if (nL[dd] > 2) {           // rare exact tail
                        const size_t w = (size_t)(b*DD + d) * DD;
                        for (int k = 2; k < nL[dd]; ++k)
                            acc = fmaf(g_aval[w + k], vrow[g_eidx[w + k]], acc);
                    }
                    orow[d] = fmaf(g, acc, xrow[d]);
                }
            }
        }
        __syncthreads();
    }
    #undef LDG2
    #undef STS2
}

// ---------------------------------------------------------------------------
extern "C" void kernel_launch(void* const* d_in, const int* in_sizes, int n_in,
                              void* d_out, int out_size)
{
    const float* x  = (const float*)d_in[0];
    const float* Wq = (const float*)d_in[1];
    const float* bq = (const float*)d_in[2];
    const float* Wk = (const float*)d_in[3];
    const float* bk = (const float*)d_in[4];
    const float* Wv = (const float*)d_in[5];
    const float* bv = (const float*)d_in[6];
    const float* gm = (const float*)d_in[7];
    float* out = (float*)d_out;

    void* eptr = nullptr;
    cudaGetSymbolAddress(&eptr, g_energy);
    cudaMemsetAsync(eptr, 0, sizeof(double)*BB*DD*DD, 0);

    cudaFuncSetAttribute(energy_k, cudaFuncAttributeMaxDynamicSharedMemorySize,
                         E_FLOATS * (int)sizeof(float));
    energy_k<<<dim3(PP/PCHUNK, BB), 256, E_FLOATS*sizeof(float)>>>(x, Wq, bq, Wk, bk);

    softmax_k<<<(BB*DD*32 + 127)/128, 128>>>();

    cudaFuncSetAttribute(outs_k, cudaFuncAttributeMaxDynamicSharedMemorySize,
                         S_FLOATS * (int)sizeof(float));
    outs_k<<<dim3(PP/OPB, BB), 256, S_FLOATS*sizeof(float)>>>(x, Wv, bv, gm, out);
}

// round 10
// speedup vs baseline: 1.1209x; 1.1209x over previous
#include <cuda_runtime.h>
#include <cstdint>

#define BB 2
#define CC 64
#define CQ 16
#define DD 96
#define PP 9216                    // H*W
#define PDSTRIDE (PP*DD)           // per-channel stride in x
#define CPD (CC*PDSTRIDE)          // per-batch stride in x
#define PCHUNK 32                  // p per block (energy), 2 per iteration
#define PCOUT 16                   // p per block (out)

typedef unsigned long long u64;

__device__ double g_energy[BB*DD*DD];
__device__ int    g_nnz [BB*DD];
__device__ int    g_eidx[BB*DD*DD];
__device__ float  g_aval[BB*DD*DD];

// ---- packed f32x2 helpers (FFMA2 path only reachable via PTX) ----
__device__ __forceinline__ u64 pk2(float lo, float hi) {
    u64 r; asm("mov.b64 %0, {%1, %2};" : "=l"(r) : "f"(lo), "f"(hi)); return r;
}
__device__ __forceinline__ u64 bc2(float v) { return pk2(v, v); }
__device__ __forceinline__ void up2(float& lo, float& hi, u64 v) {
    asm("mov.b64 {%0, %1}, %2;" : "=f"(lo), "=f"(hi) : "l"(v));
}
__device__ __forceinline__ u64 ffma2(u64 a, u64 b, u64 c) {
    u64 d; asm("fma.rn.f32x2 %0, %1, %2, %3;" : "=l"(d) : "l"(a), "l"(b), "l"(c));
    return d;
}

// ===========================================================================
// Kernel A (R9 verbatim, measured 357us): 2 slabs/iter; QK warp-split
// (2 cq x 3 d-pairs per thread); accum over both slabs (R3 tile).
// ===========================================================================
#define WQS 68                          // padded weight stride (float4-clean)
#define E_WQ 0
#define E_WK (E_WQ + CQ*WQS)            // 1088
#define E_X  (E_WK + CQ*WQS)            // 2176
#define E_Q  (E_X + 2*CC*DD)            // 14464
#define E_K  (E_Q + 2*CQ*DD)            // 17536
#define E_FLOATS (E_K + 2*CQ*DD)        // 20608 floats = 82432 B

__global__ void __launch_bounds__(256, 2) energy_k(
    const float* __restrict__ x,
    const float* __restrict__ Wq, const float* __restrict__ bq,
    const float* __restrict__ Wk, const float* __restrict__ bk)
{
    extern __shared__ __align__(16) float esm[];
    float* sWq = esm + E_WQ;
    float* sWk = esm + E_WK;
    float* sX0 = esm + E_X;             // slab s at +s*CC*DD
    float* sQ0 = esm + E_Q;             // slab s at +s*CQ*DD
    float* sK0 = esm + E_K;

    const int t  = threadIdx.x;
    const int b  = blockIdx.y;
    const int p0 = blockIdx.x * PCHUNK;

    for (int i = t; i < CQ*CC; i += 256) {
        const int cq = i >> 6, c = i & 63;
        sWq[cq*WQS + c] = Wq[i];
        sWk[cq*WQS + c] = Wk[i];
    }

    const int sh  = t >> 7;             // slab half
    const int u   = (t >> 4) & 7;       // cq pair {2u, 2u+1}
    const int dxb = 6 * (t & 15);
    const float bq0 = bq[2*u], bq1 = bq[2*u+1];
    const float bk0 = bk[2*u], bk1 = bk[2*u+1];

    const int tx = t & 15;
    const int ty = t >> 4;

    u64 acc[6][3];
    #pragma unroll
    for (int i = 0; i < 6; ++i)
        #pragma unroll
        for (int j = 0; j < 3; ++j) acc[i][j] = 0ull;

    const float* xb = x + (size_t)b * CPD;

    float4 r4[12];
    #define LDG2(PBASE) {                                                       \
        _Pragma("unroll")                                                       \
        for (int rr = 0; rr < 12; ++rr) {                                       \
            const int idx = t + rr*256;                                         \
            const int s = (rr >= 6);                                            \
            const int j = idx - s*1536;                                         \
            const int c = j / 24, d4 = j - c*24;                                \
            r4[rr] = *reinterpret_cast<const float4*>(                          \
                xb + (size_t)c * PDSTRIDE + (size_t)((PBASE) + s) * DD + 4*d4); } }
    #define STS2() {                                                            \
        _Pragma("unroll")                                                       \
        for (int rr = 0; rr < 12; ++rr) {                                       \
            const int idx = t + rr*256;                                         \
            const int s = (rr >= 6);                                            \
            const int j = idx - s*1536;                                         \
            const int c = j / 24, d4 = j - c*24;                                \
            *reinterpret_cast<float4*>(&sX0[s*(CC*DD) + c*DD + 4*d4]) = r4[rr]; } }

    LDG2(p0);

    for (int it = 0; it < PCHUNK/2; ++it) {
        STS2();
        __syncthreads();

        // ---- QK for my slab: 2 cq x 3 d-pairs, weights via float4/4c ----
        {
            const float* sX = sX0 + sh*(CC*DD);
            u64 qa0[3], qa1[3], ka0[3], ka1[3];
            #pragma unroll
            for (int j = 0; j < 3; ++j) {
                qa0[j] = bc2(bq0); qa1[j] = bc2(bq1);
                ka0[j] = bc2(bk0); ka1[j] = bc2(bk1);
            }
            #pragma unroll 4
            for (int c4 = 0; c4 < CC; c4 += 4) {
                const float4 wq40 = *reinterpret_cast<const float4*>(&sWq[(2*u)*WQS + c4]);
                const float4 wq41 = *reinterpret_cast<const float4*>(&sWq[(2*u+1)*WQS + c4]);
                const float4 wk40 = *reinterpret_cast<const float4*>(&sWk[(2*u)*WQS + c4]);
                const float4 wk41 = *reinterpret_cast<const float4*>(&sWk[(2*u+1)*WQS + c4]);
                const float wq0a[4] = {wq40.x, wq40.y, wq40.z, wq40.w};
                const float wq1a[4] = {wq41.x, wq41.y, wq41.z, wq41.w};
                const float wk0a[4] = {wk40.x, wk40.y, wk40.z, wk40.w};
                const float wk1a[4] = {wk41.x, wk41.y, wk41.z, wk41.w};
                #pragma unroll
                for (int cc = 0; cc < 4; ++cc) {
                    const int c = c4 + cc;
                    u64 xv[3];
                    #pragma unroll
                    for (int j = 0; j < 3; ++j)
                        xv[j] = *reinterpret_cast<const u64*>(&sX[c*DD + dxb + 2*j]);
                    const u64 wqb0 = bc2(wq0a[cc]);
                    const u64 wqb1 = bc2(wq1a[cc]);
                    const u64 wkb0 = bc2(wk0a[cc]);
                    const u64 wkb1 = bc2(wk1a[cc]);
                    #pragma unroll
                    for (int j = 0; j < 3; ++j) {
                        qa0[j] = ffma2(wqb0, xv[j], qa0[j]);
                        qa1[j] = ffma2(wqb1, xv[j], qa1[j]);
                        ka0[j] = ffma2(wkb0, xv[j], ka0[j]);
                        ka1[j] = ffma2(wkb1, xv[j], ka1[j]);
                    }
                }
            }
            float* sQ = sQ0 + sh*(CQ*DD);
            float* sK = sK0 + sh*(CQ*DD);
            #pragma unroll
            for (int j = 0; j < 3; ++j) {
                *reinterpret_cast<u64*>(&sQ[(2*u)*DD   + dxb + 2*j]) = qa0[j];
                *reinterpret_cast<u64*>(&sQ[(2*u+1)*DD + dxb + 2*j]) = qa1[j];
                *reinterpret_cast<u64*>(&sK[(2*u)*DD   + dxb + 2*j]) = ka0[j];
                *reinterpret_cast<u64*>(&sK[(2*u+1)*DD + dxb + 2*j]) = ka1[j];
            }
        }

        if (it + 1 < PCHUNK/2) LDG2(p0 + 2*(it+1));   // overlap with accum
        __syncthreads();

        // ---- accum both slabs ----
        #pragma unroll
        for (int s = 0; s < 2; ++s) {
            const float* sQ = sQ0 + s*(CQ*DD);
            const float* sK = sK0 + s*(CQ*DD);
            #pragma unroll 2
            for (int cq = 0; cq < CQ; ++cq) {
                u64 kv[3];
                #pragma unroll
                for (int j = 0; j < 3; ++j)
                    kv[j] = *reinterpret_cast<const u64*>(&sK[cq*DD + 6*ty + 2*j]);
                #pragma unroll
                for (int i = 0; i < 6; ++i) {
                    const u64 qb = bc2(sQ[cq*DD + tx + 16*i]);
                    #pragma unroll
                    for (int j = 0; j < 3; ++j)
                        acc[i][j] = ffma2(qb, kv[j], acc[i][j]);
                }
            }
        }
        __syncthreads();
    }

    const size_t eb = (size_t)b * DD * DD;
    #pragma unroll
    for (int i = 0; i < 6; ++i)
        #pragma unroll
        for (int j = 0; j < 3; ++j) {
            float lo, hi;
            up2(lo, hi, acc[i][j]);
            const size_t base = eb + (size_t)(tx + 16*i)*DD + (6*ty + 2*j);
            atomicAdd(&g_energy[base],     (double)lo);
            atomicAdd(&g_energy[base + 1], (double)hi);
        }
    #undef LDG2
    #undef STS2
}

// ===========================================================================
// Kernel B: row softmax + compaction (a > 1e-8). One warp per (b,d) row.
// ===========================================================================
#define ATHRESH 1e-8f

__global__ void __launch_bounds__(128) softmax_k()
{
    const int w    = (blockIdx.x * blockDim.x + threadIdx.x) >> 5;
    const int lane = threadIdx.x & 31;
    if (w >= BB*DD) return;

    const double* er = g_energy + (size_t)w * DD;
    float v0 = (float)er[lane];
    float v1 = (float)er[lane + 32];
    float v2 = (float)er[lane + 64];

    float m = fmaxf(v0, fmaxf(v1, v2));
    #pragma unroll
    for (int o = 16; o > 0; o >>= 1) m = fmaxf(m, __shfl_xor_sync(0xffffffffu, m, o));

    float e0 = expf(v0 - m), e1 = expf(v1 - m), e2 = expf(v2 - m);
    float s = e0 + e1 + e2;
    #pragma unroll
    for (int o = 16; o > 0; o >>= 1) s += __shfl_xor_sync(0xffffffffu, s, o);

    const float inv = 1.0f / s;
    const float a[3] = { e0 * inv, e1 * inv, e2 * inv };

    int* ei = g_eidx + (size_t)w * DD;
    float* av = g_aval + (size_t)w * DD;
    const unsigned lmask = (1u << lane) - 1u;
    int base = 0;
    #pragma unroll
    for (int sct = 0; sct < 3; ++sct) {
        const bool keep = a[sct] > ATHRESH;
        const unsigned mask = __ballot_sync(0xffffffffu, keep);
        if (keep) {
            const int idx = base + __popc(mask & lmask);
            ei[idx] = lane + 32*sct;
            av[idx] = a[sct];
        }
        base += __popc(mask);
    }
    if (lane == 0) g_nnz[w] = base;
}

// ===========================================================================
// Kernel C (R7 verbatim, measured ~570us within 1016 total):
// out[b,c,p,d] = gamma * sum_{k in list(d)} a_k * V[c,e_k] + x[c,p,d]
// V = Wv X_p + bv (4c x 3 e-pair FFMA2 tile). Top-2 list entries cached in
// registers; nnz>2 tail from global (rare). SMEM ~88KB -> 2 CTAs/SM.
// ===========================================================================
#define VTS 98
#define O_WV  0
#define O_X0  (O_WV + CC*CC*4)                  // 16384
#define O_V   (O_X0 + 2*CC*DD*4)                // 65536
#define O_TOTAL (O_V + CC*VTS*4)                // 90624 bytes

__global__ void __launch_bounds__(256, 2) out_k(
    const float* __restrict__ x, const float* __restrict__ Wv,
    const float* __restrict__ bv, const float* __restrict__ gamma,
    float* __restrict__ out)
{
    extern __shared__ __align__(16) unsigned char osm[];
    float* sWv  = (float*)(osm + O_WV);
    float* sXb[2] = { (float*)(osm + O_X0), (float*)(osm + O_X0) + CC*DD };
    float* sV   = (float*)(osm + O_V);          // [c][e] stride 98

    const int t  = threadIdx.x;
    const int b  = blockIdx.y;
    const int p0 = blockIdx.x * PCOUT;
    const int tx = t & 15;                      // e-group for V compute
    const int ty = t >> 4;                      // c-group for V compute
    const int exb = 6 * tx;
    const int lane = t & 31;
    const int wrp  = t >> 5;

    for (int i = t; i < CC*CC; i += 256) sWv[i] = Wv[i];

    // ---- cache top-2 attn entries per owned d-row in registers ----
    int   nL[3], e0L[3], e1L[3];
    float a0L[3], a1L[3];
    #pragma unroll
    for (int dd = 0; dd < 3; ++dd) {
        const int d = lane + 32*dd;
        const int w = b*DD + d;
        const int n = g_nnz[w];
        nL[dd]  = n;
        e0L[dd] = g_eidx[(size_t)w*DD];
        a0L[dd] = g_aval[(size_t)w*DD];
        e1L[dd] = (n > 1) ? g_eidx[(size_t)w*DD + 1] : 0;
        a1L[dd] = (n > 1) ? g_aval[(size_t)w*DD + 1] : 0.f;
    }

    const float g = gamma[0];
    float bvv[4];
    #pragma unroll
    for (int k = 0; k < 4; ++k) bvv[k] = bv[4*ty + k];

    const float* xb = x   + (size_t)b * CPD;
    float*       ob = out + (size_t)b * CPD;

    float2 r[12];
    #define LDG_SLAB(P)  {                                                      \
        const float* xp = xb + (size_t)(P) * DD;                                \
        _Pragma("unroll")                                                       \
        for (int rr = 0; rr < 12; ++rr) {                                       \
            int i2 = t + rr*256;                                                \
            int c = i2 / 48, dp = i2 % 48;                                      \
            r[rr] = *reinterpret_cast<const float2*>(xp + (size_t)c * PDSTRIDE + 2*dp); } }
    #define STS_SLAB(BUF) {                                                     \
        _Pragma("unroll")                                                       \
        for (int rr = 0; rr < 12; ++rr) {                                       \
            int i2 = t + rr*256;                                                \
            int c = i2 / 48, dp = i2 % 48;                                      \
            *reinterpret_cast<float2*>(&(BUF)[c*DD + 2*dp]) = r[rr]; } }

    LDG_SLAB(p0);
    STS_SLAB(sXb[0]);
    __syncthreads();                            // Wv + X0 visible

    for (int pp = 0; pp < PCOUT; ++pp) {
        const int p = p0 + pp;
        const float* sX = sXb[pp & 1];

        if (pp + 1 < PCOUT) LDG_SLAB(p0 + pp + 1);

        // ---- V = Wv X + bv  (4 c x 3 e-pairs per thread) ----
        {
            u64 vv[4][3];
            #pragma unroll
            for (int k = 0; k < 4; ++k)
                #pragma unroll
                for (int j = 0; j < 3; ++j) vv[k][j] = bc2(bvv[k]);

            #pragma unroll 2
            for (int c2 = 0; c2 < CC; c2 += 2) {
                u64 x0[3], x1[3];
                #pragma unroll
                for (int j = 0; j < 3; ++j) {
                    x0[j] = *reinterpret_cast<const u64*>(&sX[c2*DD + exb + 2*j]);
                    x1[j] = *reinterpret_cast<const u64*>(&sX[(c2+1)*DD + exb + 2*j]);
                }
                #pragma unroll
                for (int k = 0; k < 4; ++k) {
                    const u64 w2 = *reinterpret_cast<const u64*>(&sWv[(4*ty + k)*CC + c2]);
                    float wlo, whi; up2(wlo, whi, w2);
                    const u64 wb0 = bc2(wlo), wb1 = bc2(whi);
                    #pragma unroll
                    for (int j = 0; j < 3; ++j) {
                        vv[k][j] = ffma2(wb0, x0[j], vv[k][j]);
                        vv[k][j] = ffma2(wb1, x1[j], vv[k][j]);
                    }
                }
            }
            #pragma unroll
            for (int k = 0; k < 4; ++k)
                #pragma unroll
                for (int j = 0; j < 3; ++j)
                    *reinterpret_cast<u64*>(&sV[(4*ty + k)*VTS + exb + 2*j]) = vv[k][j];
        }
        __syncthreads();                        // V ready

        // ---- gather from registers: lanes over d (coalesced STG), warps over c ----
        #pragma unroll
        for (int ci = 0; ci < 8; ++ci) {
            const int c = wrp + 8*ci;
            const float* vrow = &sV[c*VTS];
            const float* xrow = &sX[c*DD];
            float* orow = ob + (size_t)c * PDSTRIDE + (size_t)p * DD;
            #pragma unroll
            for (int dd = 0; dd < 3; ++dd) {
                const int d = lane + 32*dd;
                float acc = a0L[dd] * vrow[e0L[dd]];
                if (nL[dd] > 1) acc = fmaf(a1L[dd], vrow[e1L[dd]], acc);
                if (nL[dd] > 2) {               // rare exact tail from global
                    const size_t w = (size_t)(b*DD + d) * DD;
                    for (int k = 2; k < nL[dd]; ++k)
                        acc = fmaf(g_aval[w + k], vrow[g_eidx[w + k]], acc);
                }
                orow[d] = fmaf(g, acc, xrow[d]);
            }
        }

        if (pp + 1 < PCOUT) STS_SLAB(sXb[(pp + 1) & 1]);
        __syncthreads();                        // gather done; next X ready
    }
    #undef LDG_SLAB
    #undef STS_SLAB
}

// ---------------------------------------------------------------------------
extern "C" void kernel_launch(void* const* d_in, const int* in_sizes, int n_in,
                              void* d_out, int out_size)
{
    const float* x  = (const float*)d_in[0];
    const float* Wq = (const float*)d_in[1];
    const float* bq = (const float*)d_in[2];
    const float* Wk = (const float*)d_in[3];
    const float* bk = (const float*)d_in[4];
    const float* Wv = (const float*)d_in[5];
    const float* bv = (const float*)d_in[6];
    const float* gm = (const float*)d_in[7];
    float* out = (float*)d_out;

    void* eptr = nullptr;
    cudaGetSymbolAddress(&eptr, g_energy);
    cudaMemsetAsync(eptr, 0, sizeof(double)*BB*DD*DD, 0);

    cudaFuncSetAttribute(energy_k, cudaFuncAttributeMaxDynamicSharedMemorySize,
                         E_FLOATS * (int)sizeof(float));
    energy_k<<<dim3(PP/PCHUNK, BB), 256, E_FLOATS*sizeof(float)>>>(x, Wq, bq, Wk, bk);

    softmax_k<<<(BB*DD*32 + 127)/128, 128>>>();

    cudaFuncSetAttribute(out_k, cudaFuncAttributeMaxDynamicSharedMemorySize, O_TOTAL);
    out_k<<<dim3(PP/PCOUT, BB), 256, O_TOTAL>>>(x, Wv, bv, gm, out);
}